// round 5
// baseline (speedup 1.0000x reference)
#include <cuda_runtime.h>
#include <cstdint>

#define N_NODES 100000
#define D_FEAT  64
#define SCAN_T  1024

// Scratch (allocation-free rule: __device__ globals)
__device__ float g_x1 [N_NODES * D_FEAT];   // x1 rows (25.6 MB)
__device__ int   g_cnt[N_NODES];            // in-degree (histogram)
__device__ int   g_off[N_NODES];            // CSR row offsets (exclusive scan)
__device__ int   g_cur[N_NODES];            // fill cursors
__device__ int   g_csr[1700000];            // CSR src ids (headroom over 1.6M)
__device__ int   g_is64;                    // edge-index dtype flag

// ---------------------------------------------------------------------------
// Prep: zero histogram counters + probe edge-index dtype (int64 vs int32).
// ---------------------------------------------------------------------------
__global__ __launch_bounds__(256)
void prep_kernel(const long long* __restrict__ ei) {
    if (blockIdx.x == 0 && threadIdx.x == 0) {
        int ok64 = 1;
        #pragma unroll
        for (int i = 0; i < 16; i++) {
            long long v = ei[i];
            if (v < 0 || v >= N_NODES) ok64 = 0;
        }
        g_is64 = ok64;
    }
    for (int i = blockIdx.x * blockDim.x + threadIdx.x; i < N_NODES;
         i += gridDim.x * blockDim.x) {
        g_cnt[i] = 0;
    }
}

// ---------------------------------------------------------------------------
// Histogram of dst -> in-degree.
// ---------------------------------------------------------------------------
__global__ __launch_bounds__(256)
void hist_kernel(const void* __restrict__ edge_buf, int n_edges) {
    int e = blockIdx.x * blockDim.x + threadIdx.x;
    if (e >= n_edges) return;
    int d;
    if (g_is64) d = (int)((const long long*)edge_buf)[e + n_edges];
    else        d = ((const int*)edge_buf)[e + n_edges];
    atomicAdd(&g_cnt[d], 1);
}

// ---------------------------------------------------------------------------
// Single-block exclusive scan of g_cnt -> g_off (and init g_cur = g_off).
// Each thread owns a contiguous chunk; block-level Hillis-Steele over partials.
// ---------------------------------------------------------------------------
__global__ __launch_bounds__(SCAN_T)
void scan_kernel() {
    __shared__ int part[SCAN_T];
    int tid = threadIdx.x;
    const int chunk = (N_NODES + SCAN_T - 1) / SCAN_T;
    int lo = tid * chunk;
    int hi = lo + chunk; if (hi > N_NODES) hi = N_NODES;

    int sum = 0;
    for (int i = lo; i < hi; i++) sum += g_cnt[i];
    part[tid] = sum;
    __syncthreads();

    // inclusive scan over partials
    for (int o = 1; o < SCAN_T; o <<= 1) {
        int v = (tid >= o) ? part[tid - o] : 0;
        __syncthreads();
        part[tid] += v;
        __syncthreads();
    }
    int run = (tid == 0) ? 0 : part[tid - 1];   // exclusive prefix of my chunk

    for (int i = lo; i < hi; i++) {
        int c = g_cnt[i];
        g_off[i] = run;
        g_cur[i] = run;
        run += c;
    }
}

// ---------------------------------------------------------------------------
// Fill CSR: for each edge, grab a slot in dst's row and store src id.
// ---------------------------------------------------------------------------
__global__ __launch_bounds__(256)
void fill_kernel(const void* __restrict__ edge_buf, int n_edges) {
    int e = blockIdx.x * blockDim.x + threadIdx.x;
    if (e >= n_edges) return;
    int s, d;
    if (g_is64) {
        const long long* ei = (const long long*)edge_buf;
        s = (int)ei[e];
        d = (int)ei[e + n_edges];
    } else {
        const int* ei = (const int*)edge_buf;
        s = ei[e];
        d = ei[e + n_edges];
    }
    int slot = atomicAdd(&g_cur[d], 1);
    g_csr[slot] = s;
}

// ---------------------------------------------------------------------------
// Gather aggregation: one warp per node, lane holds a float2 chunk (64 = 32*2).
// PASS1: gather features[src], mean -> write g_x1.
// PASS2: gather g_x1[src], mean -> x2, then fused cosine-gated blend -> out.
// (g_x1 referenced in device code: __device__ globals must never be passed
//  as kernel args from host — host shadow address reads as zeros via ATS.)
// ---------------------------------------------------------------------------
template <bool PASS1>
__global__ __launch_bounds__(256)
void agg_kernel(const float* __restrict__ feat, float* __restrict__ out) {
    int node = blockIdx.x * (blockDim.x >> 5) + (threadIdx.x >> 5);
    int lane = threadIdx.x & 31;
    if (node >= N_NODES) return;

    int off = g_off[node];
    int deg = g_cnt[node];
    const float* h = PASS1 ? feat : (const float*)g_x1;
    const int* row = g_csr + off;

    float2 acc = make_float2(0.f, 0.f);
    #pragma unroll 4
    for (int e = 0; e < deg; e++) {
        int s = __ldg(&row[e]);
        float2 v = __ldg((const float2*)(h + (size_t)s * D_FEAT) + lane);
        acc.x += v.x;
        acc.y += v.y;
    }

    float inv = (deg > 0) ? (1.0f / (float)deg) : 0.0f;
    float2 x2 = make_float2(acc.x * inv, acc.y * inv);

    size_t idx = (size_t)node * 32 + lane;
    if (PASS1) {
        ((float2*)g_x1)[idx] = x2;   // this is x1
    } else {
        float2 x1 = ((const float2*)g_x1)[idx];

        float dot  = x1.x * x2.x + x1.y * x2.y;
        float n1sq = x1.x * x1.x + x1.y * x1.y;
        float n2sq = x2.x * x2.x + x2.y * x2.y;
        #pragma unroll
        for (int o = 16; o > 0; o >>= 1) {
            dot  += __shfl_xor_sync(0xFFFFFFFFu, dot,  o);
            n1sq += __shfl_xor_sync(0xFFFFFFFFu, n1sq, o);
            n2sq += __shfl_xor_sync(0xFFFFFFFFu, n2sq, o);
        }
        float w = dot / fmaxf(sqrtf(n1sq) * sqrtf(n2sq), 1e-8f);

        float2 o2;
        o2.x = w * x2.x + (1.0f - w) * x1.x;
        o2.y = w * x2.y + (1.0f - w) * x1.y;
        ((float2*)out)[idx] = o2;
    }
}

// ---------------------------------------------------------------------------
// Launch
// ---------------------------------------------------------------------------
extern "C" void kernel_launch(void* const* d_in, const int* in_sizes, int n_in,
                              void* d_out, int out_size) {
    const float* features = (const float*)d_in[0];
    const void*  edge_buf = d_in[1];
    int n_edges = in_sizes[1] / 2;

    int eblocks = (n_edges + 255) / 256;
    int nblocks = (N_NODES * 32 + 255) / 256;   // warp per node, 8 nodes/block

    // CSR build
    prep_kernel<<<512, 256>>>((const long long*)edge_buf);
    hist_kernel<<<eblocks, 256>>>(edge_buf, n_edges);
    scan_kernel<<<1, SCAN_T>>>();
    fill_kernel<<<eblocks, 256>>>(edge_buf, n_edges);

    // Two gather passes (pass 2 fuses the cosine blend epilogue)
    agg_kernel<true ><<<nblocks, 256>>>(features, nullptr);
    agg_kernel<false><<<nblocks, 256>>>(nullptr, (float*)d_out);
}